// round 9
// baseline (speedup 1.0000x reference)
#include <cuda_runtime.h>

#define KSZ   5
#define CIN   3
#define BATCH 2
#define HH    48
#define KN    16
#define OH    44
#define PP    1936            // OH*OH
#define IMG_ELEMS (CIN*HH*HH) // 6912
#define WSZ   (CIN*KSZ*KSZ)   // 75

#define TILE    128
#define NT      16            // tiles per dim
#define NUPPER  (NT * (NT + 1) / 2)   // 136 upper-triangular tiles
#define MUBLK   8             // mu blocks per batch (2 kn planes each)
#define QV      (PP / 4)      // 484 float4 per row

typedef unsigned long long u64;

// 30 MB scratch for the unscaled Gram matrix xxT[b, p, q]
__device__ float g_xxT[(size_t)BATCH * PP * PP];

__device__ __forceinline__ u64 pack2(float lo, float hi) {
    u64 r; asm("mov.b64 %0, {%1,%2};" : "=l"(r) : "f"(lo), "f"(hi)); return r;
}
__device__ __forceinline__ void fma2(u64 &d, u64 a, u64 b) {
    asm("fma.rn.f32x2 %0, %1, %2, %0;" : "+l"(d) : "l"(a), "l"(b));
}
__device__ __forceinline__ float2 unpack2(u64 v) {
    float2 f; asm("mov.b64 {%0,%1}, %2;" : "=f"(f.x), "=f"(f.y) : "l"(v)); return f;
}

// ---------------------------------------------------------------------------
// Kernel A: xxT[b,p,q] = sum_f xm[b,p,f] * xm[b,q,f]   (+ fused mu conv)
// Grid (144, 1, 2) = 288 CTAs: exactly one wave at 2 CTAs/SM (<= 296).
// x < 136  : upper-triangular 128x128 Gram tile, stored normal + mirrored.
// x >= 136 : mu conv, 2 kn planes per block, from SMEM image + SMEM weights.
// The mu blocks (~2.6us) hide under the gram tiles (~10us) in the same wave.
// ---------------------------------------------------------------------------
__global__ __launch_bounds__(256, 2)
void vdp_gram_kernel(const float* __restrict__ mu_in,
                     const float* __restrict__ w_mu,
                     float* __restrict__ mu_out)
{
    __shared__ float img[IMG_ELEMS];
    __shared__ float wgt[2 * WSZ];

    const int tid = threadIdx.x;
    const int b   = blockIdx.z;

    // Load per-batch image (27.6 KB) into SMEM
    const float* src = mu_in + b * IMG_ELEMS;
    for (int i = tid; i < IMG_ELEMS; i += 256) img[i] = src[i];

    if (blockIdx.x >= NUPPER) {
        // ---------------- mean conv: 2 kn planes per block --------------------
        const int kn0 = (blockIdx.x - NUPPER) * 2;
        if (tid < 2 * WSZ) wgt[tid] = w_mu[kn0 * WSZ + tid];
        __syncthreads();

        #pragma unroll
        for (int half = 0; half < 2; half++) {
            const int kn = kn0 + half;
            const float* w = &wgt[half * WSZ];
            float* outp = mu_out + ((size_t)b * KN + kn) * (OH * OH);
            #pragma unroll
            for (int k = 0; k < 8; k++) {
                int pos = tid + k * 256;
                if (pos >= OH * OH) break;
                int oy = pos / OH, ox = pos - oy * OH;
                float acc = 0.0f;
                #pragma unroll
                for (int c = 0; c < CIN; c++)
                    #pragma unroll
                    for (int i = 0; i < KSZ; i++)
                        #pragma unroll
                        for (int j = 0; j < KSZ; j++)
                            acc = fmaf(img[c * HH * HH + (oy + i) * HH + ox + j],
                                       w[c * KSZ * KSZ + i * KSZ + j], acc);
                outp[pos] = acc;
            }
        }
        return;
    }
    __syncthreads();

    // Map linear tile index -> (ti, tj) with ti <= tj
    int ti = 0, rem = blockIdx.x;
    while (rem >= NT - ti) { rem -= NT - ti; ti++; }
    const int tj = ti + rem;

    const int tx = tid & 15;
    const int ty = tid >> 4;
    const int p0 = ti * TILE;
    const int q0 = tj * TILE;

    int basep[8], baseq[8];
    #pragma unroll
    for (int r = 0; r < 8; r++) {
        int p = p0 + ty * 8 + r;
        int pc = (p < PP) ? p : 0;
        int ph = pc / OH, pw = pc - ph * OH;
        basep[r] = ph * HH + pw;
    }
    #pragma unroll
    for (int s = 0; s < 8; s++) {
        int q = q0 + tx + s * 16;
        int qc = (q < PP) ? q : 0;
        int qh = qc / OH, qw = qc - qh * OH;
        baseq[s] = qh * HH + qw;
    }

    u64 acc[8][4];
    #pragma unroll
    for (int r = 0; r < 8; r++)
        #pragma unroll
        for (int h = 0; h < 4; h++) acc[r][h] = 0ULL;

    #pragma unroll 1
    for (int c = 0; c < CIN; c++) {
        int bp[8], bq[8];
        const int coff = c * (HH * HH);
        #pragma unroll
        for (int r = 0; r < 8; r++) bp[r] = basep[r] + coff;
        #pragma unroll
        for (int s = 0; s < 8; s++) bq[s] = baseq[s] + coff;

        #pragma unroll
        for (int i = 0; i < KSZ; i++) {
            #pragma unroll
            for (int j = 0; j < KSZ; j++) {
                const int off = i * HH + j;
                float av[8], bv[8];
                #pragma unroll
                for (int r = 0; r < 8; r++) av[r] = img[bp[r] + off];
                #pragma unroll
                for (int s = 0; s < 8; s++) bv[s] = img[bq[s] + off];

                u64 avp[8], bvp[4];
                #pragma unroll
                for (int r = 0; r < 8; r++) avp[r] = pack2(av[r], av[r]);
                #pragma unroll
                for (int h = 0; h < 4; h++) bvp[h] = pack2(bv[2*h], bv[2*h+1]);

                #pragma unroll
                for (int r = 0; r < 8; r++)
                    #pragma unroll
                    for (int h = 0; h < 4; h++)
                        fma2(acc[r][h], avp[r], bvp[h]);
            }
        }
    }

    float* gbase = g_xxT + (size_t)b * PP * PP;

    // Normal-orientation store of tile (ti, tj)
    #pragma unroll
    for (int r = 0; r < 8; r++) {
        int p = p0 + ty * 8 + r;
        if (p >= PP) continue;
        float* row = gbase + (size_t)p * PP;
        #pragma unroll
        for (int h = 0; h < 4; h++) {
            float2 f = unpack2(acc[r][h]);
            int q1 = q0 + tx + 32 * h;
            int q2 = q1 + 16;
            if (q1 < PP) row[q1] = f.x;
            if (q2 < PP) row[q2] = f.y;
        }
    }

    // Mirrored store of tile (tj, ti): row q, 8 consecutive p per thread.
    if (ti != tj) {
        const int pbase = p0 + ty * 8;
        #pragma unroll
        for (int s = 0; s < 8; s++) {
            int q = q0 + tx + 16 * s;
            if (q >= PP) continue;
            float4 v0, v1;
            {
                float2 a0 = unpack2(acc[0][s >> 1]);
                float2 a1 = unpack2(acc[1][s >> 1]);
                float2 a2 = unpack2(acc[2][s >> 1]);
                float2 a3 = unpack2(acc[3][s >> 1]);
                float2 a4 = unpack2(acc[4][s >> 1]);
                float2 a5 = unpack2(acc[5][s >> 1]);
                float2 a6 = unpack2(acc[6][s >> 1]);
                float2 a7 = unpack2(acc[7][s >> 1]);
                if (s & 1) {
                    v0 = make_float4(a0.y, a1.y, a2.y, a3.y);
                    v1 = make_float4(a4.y, a5.y, a6.y, a7.y);
                } else {
                    v0 = make_float4(a0.x, a1.x, a2.x, a3.x);
                    v1 = make_float4(a4.x, a5.x, a6.x, a7.x);
                }
            }
            float* row = gbase + (size_t)q * PP + pbase;
            if (pbase < PP)     *(float4*)row       = v0;
            if (pbase + 4 < PP) *(float4*)(row + 4) = v1;
        }
    }
}

// ---------------------------------------------------------------------------
// Kernel B (measured-good R7 config, pure): sigma = xxT * sp[kn]
// One float4 per thread; consecutive lanes -> consecutive 16B (dense 512B
// per STG.128). 16 streaming stores per thread.
// ---------------------------------------------------------------------------
__global__ __launch_bounds__(256)
void vdp_scale_kernel(const float* __restrict__ w_sigma,
                      float* __restrict__ sigma)
{
    __shared__ float sp[KN];
    if (threadIdx.x < KN) sp[threadIdx.x] = log1pf(expf(w_sigma[threadIdx.x]));
    __syncthreads();

    int idx = blockIdx.x * 256 + threadIdx.x;
    const int total = BATCH * PP * QV;
    if (idx >= total) return;

    int qv = idx % QV;
    int p  = (idx / QV) % PP;
    int b  = idx / (QV * PP);

    const float4 v = __ldcg((const float4*)&g_xxT[((size_t)b * PP + p) * PP + qv * 4]);

    const size_t planeStride = (size_t)PP * PP;
    float* o = sigma + ((size_t)b * KN) * planeStride + (size_t)p * PP + qv * 4;

    #pragma unroll
    for (int kn = 0; kn < KN; kn++) {
        const float s = sp[kn];
        float4 w;
        w.x = v.x * s; w.y = v.y * s; w.z = v.z * s; w.w = v.w * s;
        __stcs((float4*)o, w);
        o += planeStride;
    }
}

extern "C" void kernel_launch(void* const* d_in, const int* in_sizes, int n_in,
                              void* d_out, int out_size)
{
    const float* mu_in   = (const float*)d_in[0];
    const float* w_mu    = (const float*)d_in[1];
    const float* w_sigma = (const float*)d_in[2];

    float* out    = (float*)d_out;
    float* mu_out = out;
    float* sigma  = out + (size_t)BATCH * KN * OH * OH;

    dim3 gridA(NUPPER + MUBLK, 1, BATCH);   // 288 CTAs: one wave at 2/SM
    vdp_gram_kernel<<<gridA, 256>>>(mu_in, w_mu, mu_out);

    const int totalB = BATCH * PP * QV;     // 1,874,048
    vdp_scale_kernel<<<(totalB + 255) / 256, 256>>>(w_sigma, sigma);
}

// round 10
// speedup vs baseline: 1.1119x; 1.1119x over previous
#include <cuda_runtime.h>

#define KSZ   5
#define CIN   3
#define BATCH 2
#define HH    48
#define KN    16
#define OH    44
#define PP    1936            // OH*OH
#define IMG_ELEMS (CIN*HH*HH) // 6912
#define WSZ   (CIN*KSZ*KSZ)   // 75

#define TILE    128
#define NT      16            // tiles per dim
#define NUPPER  (NT * (NT + 1) / 2)   // 136 upper-triangular tiles
#define QV      (PP / 4)      // 484 float4 per row

#define MU_BLOCKS    (BATCH * KN)                      // 32, scheduled FIRST
#define SCALE_TOTAL  (BATCH * PP * QV)                 // 1,874,048 vec4 units
#define SCALE_BLOCKS ((SCALE_TOTAL + 255) / 256)       // 7321

typedef unsigned long long u64;

// 30 MB scratch for the unscaled Gram matrix xxT[b, p, q]
__device__ float g_xxT[(size_t)BATCH * PP * PP];

__device__ __forceinline__ u64 pack2(float lo, float hi) {
    u64 r; asm("mov.b64 %0, {%1,%2};" : "=l"(r) : "f"(lo), "f"(hi)); return r;
}
__device__ __forceinline__ void fma2(u64 &d, u64 a, u64 b) {
    asm("fma.rn.f32x2 %0, %1, %2, %0;" : "+l"(d) : "l"(a), "l"(b));
}
__device__ __forceinline__ float2 unpack2(u64 v) {
    float2 f; asm("mov.b64 {%0,%1}, %2;" : "=f"(f.x), "=f"(f.y) : "l"(v)); return f;
}

// ---------------------------------------------------------------------------
// Kernel A (exact measured-good R8 version): pure Gram.
// Grid (136, 1, 2) = 272 CTAs: one wave at 2 CTAs/SM. Each CTA computes an
// upper-triangular 128x128 tile and stores it twice (normal + mirrored).
// ---------------------------------------------------------------------------
__global__ __launch_bounds__(256, 2)
void vdp_gram_kernel(const float* __restrict__ mu_in)
{
    __shared__ float img[IMG_ELEMS];

    const int tid = threadIdx.x;
    const int b   = blockIdx.z;

    const float* src = mu_in + b * IMG_ELEMS;
    for (int i = tid; i < IMG_ELEMS; i += 256) img[i] = src[i];
    __syncthreads();

    int ti = 0, rem = blockIdx.x;
    while (rem >= NT - ti) { rem -= NT - ti; ti++; }
    const int tj = ti + rem;

    const int tx = tid & 15;
    const int ty = tid >> 4;
    const int p0 = ti * TILE;
    const int q0 = tj * TILE;

    int basep[8], baseq[8];
    #pragma unroll
    for (int r = 0; r < 8; r++) {
        int p = p0 + ty * 8 + r;
        int pc = (p < PP) ? p : 0;
        int ph = pc / OH, pw = pc - ph * OH;
        basep[r] = ph * HH + pw;
    }
    #pragma unroll
    for (int s = 0; s < 8; s++) {
        int q = q0 + tx + s * 16;
        int qc = (q < PP) ? q : 0;
        int qh = qc / OH, qw = qc - qh * OH;
        baseq[s] = qh * HH + qw;
    }

    u64 acc[8][4];
    #pragma unroll
    for (int r = 0; r < 8; r++)
        #pragma unroll
        for (int h = 0; h < 4; h++) acc[r][h] = 0ULL;

    #pragma unroll 1
    for (int c = 0; c < CIN; c++) {
        int bp[8], bq[8];
        const int coff = c * (HH * HH);
        #pragma unroll
        for (int r = 0; r < 8; r++) bp[r] = basep[r] + coff;
        #pragma unroll
        for (int s = 0; s < 8; s++) bq[s] = baseq[s] + coff;

        #pragma unroll
        for (int i = 0; i < KSZ; i++) {
            #pragma unroll
            for (int j = 0; j < KSZ; j++) {
                const int off = i * HH + j;
                float av[8], bv[8];
                #pragma unroll
                for (int r = 0; r < 8; r++) av[r] = img[bp[r] + off];
                #pragma unroll
                for (int s = 0; s < 8; s++) bv[s] = img[bq[s] + off];

                u64 avp[8], bvp[4];
                #pragma unroll
                for (int r = 0; r < 8; r++) avp[r] = pack2(av[r], av[r]);
                #pragma unroll
                for (int h = 0; h < 4; h++) bvp[h] = pack2(bv[2*h], bv[2*h+1]);

                #pragma unroll
                for (int r = 0; r < 8; r++)
                    #pragma unroll
                    for (int h = 0; h < 4; h++)
                        fma2(acc[r][h], avp[r], bvp[h]);
            }
        }
    }

    float* gbase = g_xxT + (size_t)b * PP * PP;

    #pragma unroll
    for (int r = 0; r < 8; r++) {
        int p = p0 + ty * 8 + r;
        if (p >= PP) continue;
        float* row = gbase + (size_t)p * PP;
        #pragma unroll
        for (int h = 0; h < 4; h++) {
            float2 f = unpack2(acc[r][h]);
            int q1 = q0 + tx + 32 * h;
            int q2 = q1 + 16;
            if (q1 < PP) row[q1] = f.x;
            if (q2 < PP) row[q2] = f.y;
        }
    }

    if (ti != tj) {
        const int pbase = p0 + ty * 8;
        #pragma unroll
        for (int s = 0; s < 8; s++) {
            int q = q0 + tx + 16 * s;
            if (q >= PP) continue;
            float4 v0, v1;
            {
                float2 a0 = unpack2(acc[0][s >> 1]);
                float2 a1 = unpack2(acc[1][s >> 1]);
                float2 a2 = unpack2(acc[2][s >> 1]);
                float2 a3 = unpack2(acc[3][s >> 1]);
                float2 a4 = unpack2(acc[4][s >> 1]);
                float2 a5 = unpack2(acc[5][s >> 1]);
                float2 a6 = unpack2(acc[6][s >> 1]);
                float2 a7 = unpack2(acc[7][s >> 1]);
                if (s & 1) {
                    v0 = make_float4(a0.y, a1.y, a2.y, a3.y);
                    v1 = make_float4(a4.y, a5.y, a6.y, a7.y);
                } else {
                    v0 = make_float4(a0.x, a1.x, a2.x, a3.x);
                    v1 = make_float4(a4.x, a5.x, a6.x, a7.x);
                }
            }
            float* row = gbase + (size_t)q * PP + pbase;
            if (pbase < PP)     *(float4*)row       = v0;
            if (pbase + 4 < PP) *(float4*)(row + 4) = v1;
        }
    }
}

// ---------------------------------------------------------------------------
// Kernel B: blocks [0, 32)        : mu conv, one (b,kn) plane per block,
//                                   8 independent accumulators (ILP breaks the
//                                   load->fma latency chain); runs FIRST so it
//                                   hides under the store-bound bulk.
//           blocks [32, 32+7321)  : sigma = xxT * softplus(w_sigma[kn]),
//                                   measured-good dense-store config.
// ---------------------------------------------------------------------------
__global__ __launch_bounds__(256)
void vdp_scale_kernel(const float* __restrict__ w_sigma,
                      const float* __restrict__ mu_in,
                      const float* __restrict__ w_mu,
                      float* __restrict__ mu_out,
                      float* __restrict__ sigma)
{
    const int tid = threadIdx.x;

    if (blockIdx.x < MU_BLOCKS) {
        // ---------------- mean conv plane, 8-way ILP ----------------
        const int b  = blockIdx.x >> 4;
        const int kn = blockIdx.x & 15;
        const float* im = mu_in + b * IMG_ELEMS;
        const float* w  = w_mu + kn * WSZ;

        int base[8];
        bool valid[8];
        #pragma unroll
        for (int k = 0; k < 8; k++) {
            int pos = tid + k * 256;
            valid[k] = (pos < OH * OH);
            int pc = valid[k] ? pos : 0;
            int oy = pc / OH, ox = pc - oy * OH;
            base[k] = oy * HH + ox;
        }

        float acc[8];
        #pragma unroll
        for (int k = 0; k < 8; k++) acc[k] = 0.0f;

        #pragma unroll
        for (int c = 0; c < CIN; c++) {
            const float* imc = im + c * HH * HH;
            const float* wc  = w + c * KSZ * KSZ;
            #pragma unroll
            for (int i = 0; i < KSZ; i++) {
                #pragma unroll
                for (int j = 0; j < KSZ; j++) {
                    const float wv = __ldg(&wc[i * KSZ + j]);
                    const int off = i * HH + j;
                    #pragma unroll
                    for (int k = 0; k < 8; k++)
                        acc[k] = fmaf(__ldg(&imc[base[k] + off]), wv, acc[k]);
                }
            }
        }

        float* outp = mu_out + ((size_t)b * KN + kn) * (OH * OH);
        #pragma unroll
        for (int k = 0; k < 8; k++)
            if (valid[k]) outp[tid + k * 256] = acc[k];
        return;
    }

    __shared__ float sp[KN];
    if (tid < KN) sp[tid] = log1pf(expf(w_sigma[tid]));
    __syncthreads();

    int idx = (blockIdx.x - MU_BLOCKS) * 256 + tid;
    if (idx >= SCALE_TOTAL) return;

    int qv = idx % QV;
    int p  = (idx / QV) % PP;
    int b  = idx / (QV * PP);

    const float4 v = __ldcg((const float4*)&g_xxT[((size_t)b * PP + p) * PP + qv * 4]);

    const size_t planeStride = (size_t)PP * PP;
    float* o = sigma + ((size_t)b * KN) * planeStride + (size_t)p * PP + qv * 4;

    #pragma unroll
    for (int kn = 0; kn < KN; kn++) {
        const float s = sp[kn];
        float4 w;
        w.x = v.x * s; w.y = v.y * s; w.z = v.z * s; w.w = v.w * s;
        __stcs((float4*)o, w);
        o += planeStride;
    }
}

extern "C" void kernel_launch(void* const* d_in, const int* in_sizes, int n_in,
                              void* d_out, int out_size)
{
    const float* mu_in   = (const float*)d_in[0];
    const float* w_mu    = (const float*)d_in[1];
    const float* w_sigma = (const float*)d_in[2];

    float* out    = (float*)d_out;
    float* mu_out = out;
    float* sigma  = out + (size_t)BATCH * KN * OH * OH;

    dim3 gridA(NUPPER, 1, BATCH);   // 272 CTAs: one wave at 2/SM (pure gram)
    vdp_gram_kernel<<<gridA, 256>>>(mu_in);

    vdp_scale_kernel<<<MU_BLOCKS + SCALE_BLOCKS, 256>>>(w_sigma, mu_in, w_mu,
                                                        mu_out, sigma);
}

// round 11
// speedup vs baseline: 1.1149x; 1.0027x over previous
#include <cuda_runtime.h>

#define KSZ   5
#define CIN   3
#define BATCH 2
#define HH    48
#define KN    16
#define OH    44
#define PP    1936            // OH*OH
#define IMG_ELEMS (CIN*HH*HH) // 6912
#define WSZ   (CIN*KSZ*KSZ)   // 75

#define TILE    128
#define NT      16            // tiles per dim
#define NUPPER  (NT * (NT + 1) / 2)   // 136 upper-triangular tiles
#define QV      (PP / 4)      // 484 float4 per row

#define MU_BLOCKS    (BATCH * KN)                      // 32, scheduled FIRST
#define SCALE_TOTAL  (BATCH * PP * QV)                 // 1,874,048 vec4 units
#define SCALE_BLOCKS ((SCALE_TOTAL + 255) / 256)       // 7321

typedef unsigned long long u64;

// 30 MB scratch for the unscaled Gram matrix xxT[b, p, q]
__device__ float g_xxT[(size_t)BATCH * PP * PP];

__device__ __forceinline__ u64 pack2(float lo, float hi) {
    u64 r; asm("mov.b64 %0, {%1,%2};" : "=l"(r) : "f"(lo), "f"(hi)); return r;
}
__device__ __forceinline__ void fma2(u64 &d, u64 a, u64 b) {
    asm("fma.rn.f32x2 %0, %1, %2, %0;" : "+l"(d) : "l"(a), "l"(b));
}
__device__ __forceinline__ float2 unpack2(u64 v) {
    float2 f; asm("mov.b64 {%0,%1}, %2;" : "=f"(f.x), "=f"(f.y) : "l"(v)); return f;
}

// ---------------------------------------------------------------------------
// Kernel A (measured-good): pure Gram.
// Grid (136, 1, 2) = 272 CTAs: one wave at 2 CTAs/SM. Each CTA computes an
// upper-triangular 128x128 tile and stores it twice (normal + mirrored).
// ---------------------------------------------------------------------------
__global__ __launch_bounds__(256, 2)
void vdp_gram_kernel(const float* __restrict__ mu_in)
{
    __shared__ float img[IMG_ELEMS];

    const int tid = threadIdx.x;
    const int b   = blockIdx.z;

    const float* src = mu_in + b * IMG_ELEMS;
    for (int i = tid; i < IMG_ELEMS; i += 256) img[i] = src[i];
    __syncthreads();

    int ti = 0, rem = blockIdx.x;
    while (rem >= NT - ti) { rem -= NT - ti; ti++; }
    const int tj = ti + rem;

    const int tx = tid & 15;
    const int ty = tid >> 4;
    const int p0 = ti * TILE;
    const int q0 = tj * TILE;

    int basep[8], baseq[8];
    #pragma unroll
    for (int r = 0; r < 8; r++) {
        int p = p0 + ty * 8 + r;
        int pc = (p < PP) ? p : 0;
        int ph = pc / OH, pw = pc - ph * OH;
        basep[r] = ph * HH + pw;
    }
    #pragma unroll
    for (int s = 0; s < 8; s++) {
        int q = q0 + tx + s * 16;
        int qc = (q < PP) ? q : 0;
        int qh = qc / OH, qw = qc - qh * OH;
        baseq[s] = qh * HH + qw;
    }

    u64 acc[8][4];
    #pragma unroll
    for (int r = 0; r < 8; r++)
        #pragma unroll
        for (int h = 0; h < 4; h++) acc[r][h] = 0ULL;

    #pragma unroll 1
    for (int c = 0; c < CIN; c++) {
        int bp[8], bq[8];
        const int coff = c * (HH * HH);
        #pragma unroll
        for (int r = 0; r < 8; r++) bp[r] = basep[r] + coff;
        #pragma unroll
        for (int s = 0; s < 8; s++) bq[s] = baseq[s] + coff;

        #pragma unroll
        for (int i = 0; i < KSZ; i++) {
            #pragma unroll
            for (int j = 0; j < KSZ; j++) {
                const int off = i * HH + j;
                float av[8], bv[8];
                #pragma unroll
                for (int r = 0; r < 8; r++) av[r] = img[bp[r] + off];
                #pragma unroll
                for (int s = 0; s < 8; s++) bv[s] = img[bq[s] + off];

                u64 avp[8], bvp[4];
                #pragma unroll
                for (int r = 0; r < 8; r++) avp[r] = pack2(av[r], av[r]);
                #pragma unroll
                for (int h = 0; h < 4; h++) bvp[h] = pack2(bv[2*h], bv[2*h+1]);

                #pragma unroll
                for (int r = 0; r < 8; r++)
                    #pragma unroll
                    for (int h = 0; h < 4; h++)
                        fma2(acc[r][h], avp[r], bvp[h]);
            }
        }
    }

    float* gbase = g_xxT + (size_t)b * PP * PP;

    #pragma unroll
    for (int r = 0; r < 8; r++) {
        int p = p0 + ty * 8 + r;
        if (p >= PP) continue;
        float* row = gbase + (size_t)p * PP;
        #pragma unroll
        for (int h = 0; h < 4; h++) {
            float2 f = unpack2(acc[r][h]);
            int q1 = q0 + tx + 32 * h;
            int q2 = q1 + 16;
            if (q1 < PP) row[q1] = f.x;
            if (q2 < PP) row[q2] = f.y;
        }
    }

    if (ti != tj) {
        const int pbase = p0 + ty * 8;
        #pragma unroll
        for (int s = 0; s < 8; s++) {
            int q = q0 + tx + 16 * s;
            if (q >= PP) continue;
            float4 v0, v1;
            {
                float2 a0 = unpack2(acc[0][s >> 1]);
                float2 a1 = unpack2(acc[1][s >> 1]);
                float2 a2 = unpack2(acc[2][s >> 1]);
                float2 a3 = unpack2(acc[3][s >> 1]);
                float2 a4 = unpack2(acc[4][s >> 1]);
                float2 a5 = unpack2(acc[5][s >> 1]);
                float2 a6 = unpack2(acc[6][s >> 1]);
                float2 a7 = unpack2(acc[7][s >> 1]);
                if (s & 1) {
                    v0 = make_float4(a0.y, a1.y, a2.y, a3.y);
                    v1 = make_float4(a4.y, a5.y, a6.y, a7.y);
                } else {
                    v0 = make_float4(a0.x, a1.x, a2.x, a3.x);
                    v1 = make_float4(a4.x, a5.x, a6.x, a7.x);
                }
            }
            float* row = gbase + (size_t)q * PP + pbase;
            if (pbase < PP)     *(float4*)row       = v0;
            if (pbase + 4 < PP) *(float4*)(row + 4) = v1;
        }
    }
}

// ---------------------------------------------------------------------------
// Kernel B: blocks [0, 32)       : mu conv, 4 accumulators x 2 passes (low
//                                  register footprint so the launch-bounds cap
//                                  doesn't hurt the scale path); runs FIRST so
//                                  it hides under the store-bound bulk.
//           blocks [32, 32+7321) : sigma = xxT * softplus(w_sigma[kn]),
//                                  measured-good dense-store config.
// __launch_bounds__(256, 6) caps regs at ~42 -> scale path keeps ~34 regs
// and >=48 warps/SM occupancy.
// ---------------------------------------------------------------------------
__global__ __launch_bounds__(256, 6)
void vdp_scale_kernel(const float* __restrict__ w_sigma,
                      const float* __restrict__ mu_in,
                      const float* __restrict__ w_mu,
                      float* __restrict__ mu_out,
                      float* __restrict__ sigma)
{
    const int tid = threadIdx.x;

    if (blockIdx.x < MU_BLOCKS) {
        // ---------------- mean conv plane: 2 passes of 4-way ILP ------------
        const int b  = blockIdx.x >> 4;
        const int kn = blockIdx.x & 15;
        const float* im = mu_in + b * IMG_ELEMS;
        const float* w  = w_mu + kn * WSZ;
        float* outp = mu_out + ((size_t)b * KN + kn) * (OH * OH);

        #pragma unroll 1
        for (int pass = 0; pass < 2; pass++) {
            int base[4];
            bool valid[4];
            #pragma unroll
            for (int k = 0; k < 4; k++) {
                int pos = tid + (pass * 4 + k) * 256;
                valid[k] = (pos < OH * OH);
                int pc = valid[k] ? pos : 0;
                int oy = pc / OH, ox = pc - oy * OH;
                base[k] = oy * HH + ox;
            }

            float acc[4] = {0.f, 0.f, 0.f, 0.f};

            #pragma unroll
            for (int c = 0; c < CIN; c++) {
                const float* imc = im + c * HH * HH;
                const float* wc  = w + c * KSZ * KSZ;
                #pragma unroll
                for (int i = 0; i < KSZ; i++) {
                    #pragma unroll
                    for (int j = 0; j < KSZ; j++) {
                        const float wv = __ldg(&wc[i * KSZ + j]);
                        const int off = i * HH + j;
                        #pragma unroll
                        for (int k = 0; k < 4; k++)
                            acc[k] = fmaf(__ldg(&imc[base[k] + off]), wv, acc[k]);
                    }
                }
            }

            #pragma unroll
            for (int k = 0; k < 4; k++)
                if (valid[k]) outp[tid + (pass * 4 + k) * 256] = acc[k];
        }
        return;
    }

    __shared__ float sp[KN];
    if (tid < KN) sp[tid] = log1pf(expf(w_sigma[tid]));
    __syncthreads();

    int idx = (blockIdx.x - MU_BLOCKS) * 256 + tid;
    if (idx >= SCALE_TOTAL) return;

    int qv = idx % QV;
    int p  = (idx / QV) % PP;
    int b  = idx / (QV * PP);

    const float4 v = __ldcg((const float4*)&g_xxT[((size_t)b * PP + p) * PP + qv * 4]);

    const size_t planeStride = (size_t)PP * PP;
    float* o = sigma + ((size_t)b * KN) * planeStride + (size_t)p * PP + qv * 4;

    #pragma unroll
    for (int kn = 0; kn < KN; kn++) {
        const float s = sp[kn];
        float4 w;
        w.x = v.x * s; w.y = v.y * s; w.z = v.z * s; w.w = v.w * s;
        __stcs((float4*)o, w);
        o += planeStride;
    }
}

extern "C" void kernel_launch(void* const* d_in, const int* in_sizes, int n_in,
                              void* d_out, int out_size)
{
    const float* mu_in   = (const float*)d_in[0];
    const float* w_mu    = (const float*)d_in[1];
    const float* w_sigma = (const float*)d_in[2];

    float* out    = (float*)d_out;
    float* mu_out = out;
    float* sigma  = out + (size_t)BATCH * KN * OH * OH;

    dim3 gridA(NUPPER, 1, BATCH);   // 272 CTAs: one wave at 2/SM (pure gram)
    vdp_gram_kernel<<<gridA, 256>>>(mu_in);

    vdp_scale_kernel<<<MU_BLOCKS + SCALE_BLOCKS, 256>>>(w_sigma, mu_in, w_mu,
                                                        mu_out, sigma);
}

// round 12
// speedup vs baseline: 1.1195x; 1.0041x over previous
#include <cuda_runtime.h>

#define KSZ   5
#define CIN   3
#define BATCH 2
#define HH    48
#define KN    16
#define OH    44
#define PP    1936            // OH*OH
#define IMG_ELEMS (CIN*HH*HH) // 6912
#define WSZ   (CIN*KSZ*KSZ)   // 75

#define TILE    128
#define NT      16            // tiles per dim
#define NUPPER  (NT * (NT + 1) / 2)   // 136 upper-triangular tiles
#define QV      (PP / 4)      // 484 float4 per row

#define MU_BLOCKS    (BATCH * KN)                      // 32, scheduled FIRST
#define SCALE_TOTAL  (BATCH * PP * QV)                 // 1,874,048 vec4 units
#define SCALE_BLOCKS ((SCALE_TOTAL + 255) / 256)       // 7321

typedef unsigned long long u64;

// 30 MB scratch for the unscaled Gram matrix xxT[b, p, q]
__device__ float g_xxT[(size_t)BATCH * PP * PP];

__device__ __forceinline__ u64 pack2(float lo, float hi) {
    u64 r; asm("mov.b64 %0, {%1,%2};" : "=l"(r) : "f"(lo), "f"(hi)); return r;
}
__device__ __forceinline__ void fma2(u64 &d, u64 a, u64 b) {
    asm("fma.rn.f32x2 %0, %1, %2, %0;" : "+l"(d) : "l"(a), "l"(b));
}
__device__ __forceinline__ float2 unpack2(u64 v) {
    float2 f; asm("mov.b64 {%0,%1}, %2;" : "=f"(f.x), "=f"(f.y) : "l"(v)); return f;
}

// ---------------------------------------------------------------------------
// Kernel A (measured-good): pure Gram.
// Grid (136, 1, 2) = 272 CTAs: one wave at 2 CTAs/SM. Each CTA computes an
// upper-triangular 128x128 tile and stores it twice (normal + mirrored).
// Signals programmatic launch completion so the scale kernel can start
// filling SMs as gram CTAs drain.
// ---------------------------------------------------------------------------
__global__ __launch_bounds__(256, 2)
void vdp_gram_kernel(const float* __restrict__ mu_in)
{
    __shared__ float img[IMG_ELEMS];

    const int tid = threadIdx.x;
    const int b   = blockIdx.z;

    const float* src = mu_in + b * IMG_ELEMS;
    for (int i = tid; i < IMG_ELEMS; i += 256) img[i] = src[i];
    __syncthreads();

    int ti = 0, rem = blockIdx.x;
    while (rem >= NT - ti) { rem -= NT - ti; ti++; }
    const int tj = ti + rem;

    const int tx = tid & 15;
    const int ty = tid >> 4;
    const int p0 = ti * TILE;
    const int q0 = tj * TILE;

    int basep[8], baseq[8];
    #pragma unroll
    for (int r = 0; r < 8; r++) {
        int p = p0 + ty * 8 + r;
        int pc = (p < PP) ? p : 0;
        int ph = pc / OH, pw = pc - ph * OH;
        basep[r] = ph * HH + pw;
    }
    #pragma unroll
    for (int s = 0; s < 8; s++) {
        int q = q0 + tx + s * 16;
        int qc = (q < PP) ? q : 0;
        int qh = qc / OH, qw = qc - qh * OH;
        baseq[s] = qh * HH + qw;
    }

    u64 acc[8][4];
    #pragma unroll
    for (int r = 0; r < 8; r++)
        #pragma unroll
        for (int h = 0; h < 4; h++) acc[r][h] = 0ULL;

    #pragma unroll 1
    for (int c = 0; c < CIN; c++) {
        int bp[8], bq[8];
        const int coff = c * (HH * HH);
        #pragma unroll
        for (int r = 0; r < 8; r++) bp[r] = basep[r] + coff;
        #pragma unroll
        for (int s = 0; s < 8; s++) bq[s] = baseq[s] + coff;

        #pragma unroll
        for (int i = 0; i < KSZ; i++) {
            #pragma unroll
            for (int j = 0; j < KSZ; j++) {
                const int off = i * HH + j;
                float av[8], bv[8];
                #pragma unroll
                for (int r = 0; r < 8; r++) av[r] = img[bp[r] + off];
                #pragma unroll
                for (int s = 0; s < 8; s++) bv[s] = img[bq[s] + off];

                u64 avp[8], bvp[4];
                #pragma unroll
                for (int r = 0; r < 8; r++) avp[r] = pack2(av[r], av[r]);
                #pragma unroll
                for (int h = 0; h < 4; h++) bvp[h] = pack2(bv[2*h], bv[2*h+1]);

                #pragma unroll
                for (int r = 0; r < 8; r++)
                    #pragma unroll
                    for (int h = 0; h < 4; h++)
                        fma2(acc[r][h], avp[r], bvp[h]);
            }
        }
    }

    // Allow the dependent (scale) kernel to begin launching; its xxT readers
    // still gate on griddepcontrol.wait, which carries the memory guarantee.
    asm volatile("griddepcontrol.launch_dependents;");

    float* gbase = g_xxT + (size_t)b * PP * PP;

    #pragma unroll
    for (int r = 0; r < 8; r++) {
        int p = p0 + ty * 8 + r;
        if (p >= PP) continue;
        float* row = gbase + (size_t)p * PP;
        #pragma unroll
        for (int h = 0; h < 4; h++) {
            float2 f = unpack2(acc[r][h]);
            int q1 = q0 + tx + 32 * h;
            int q2 = q1 + 16;
            if (q1 < PP) row[q1] = f.x;
            if (q2 < PP) row[q2] = f.y;
        }
    }

    if (ti != tj) {
        const int pbase = p0 + ty * 8;
        #pragma unroll
        for (int s = 0; s < 8; s++) {
            int q = q0 + tx + 16 * s;
            if (q >= PP) continue;
            float4 v0, v1;
            {
                float2 a0 = unpack2(acc[0][s >> 1]);
                float2 a1 = unpack2(acc[1][s >> 1]);
                float2 a2 = unpack2(acc[2][s >> 1]);
                float2 a3 = unpack2(acc[3][s >> 1]);
                float2 a4 = unpack2(acc[4][s >> 1]);
                float2 a5 = unpack2(acc[5][s >> 1]);
                float2 a6 = unpack2(acc[6][s >> 1]);
                float2 a7 = unpack2(acc[7][s >> 1]);
                if (s & 1) {
                    v0 = make_float4(a0.y, a1.y, a2.y, a3.y);
                    v1 = make_float4(a4.y, a5.y, a6.y, a7.y);
                } else {
                    v0 = make_float4(a0.x, a1.x, a2.x, a3.x);
                    v1 = make_float4(a4.x, a5.x, a6.x, a7.x);
                }
            }
            float* row = gbase + (size_t)q * PP + pbase;
            if (pbase < PP)     *(float4*)row       = v0;
            if (pbase + 4 < PP) *(float4*)(row + 4) = v1;
        }
    }
}

// ---------------------------------------------------------------------------
// Kernel B: blocks [0, 32)       : mu conv (no xxT dependency -> NO wait;
//                                  fully overlaps the gram kernel under PDL).
//           blocks [32, 32+7321) : sigma = xxT * softplus(w_sigma[kn]);
//                                  prologue before griddepcontrol.wait, then
//                                  measured-good dense-store config.
// ---------------------------------------------------------------------------
__global__ __launch_bounds__(256, 6)
void vdp_scale_kernel(const float* __restrict__ w_sigma,
                      const float* __restrict__ mu_in,
                      const float* __restrict__ w_mu,
                      float* __restrict__ mu_out,
                      float* __restrict__ sigma)
{
    const int tid = threadIdx.x;

    if (blockIdx.x < MU_BLOCKS) {
        // ---------------- mean conv plane: 2 passes of 4-way ILP ------------
        const int b  = blockIdx.x >> 4;
        const int kn = blockIdx.x & 15;
        const float* im = mu_in + b * IMG_ELEMS;
        const float* w  = w_mu + kn * WSZ;
        float* outp = mu_out + ((size_t)b * KN + kn) * (OH * OH);

        #pragma unroll 1
        for (int pass = 0; pass < 2; pass++) {
            int base[4];
            bool valid[4];
            #pragma unroll
            for (int k = 0; k < 4; k++) {
                int pos = tid + (pass * 4 + k) * 256;
                valid[k] = (pos < OH * OH);
                int pc = valid[k] ? pos : 0;
                int oy = pc / OH, ox = pc - oy * OH;
                base[k] = oy * HH + ox;
            }

            float acc[4] = {0.f, 0.f, 0.f, 0.f};

            #pragma unroll
            for (int c = 0; c < CIN; c++) {
                const float* imc = im + c * HH * HH;
                const float* wc  = w + c * KSZ * KSZ;
                #pragma unroll
                for (int i = 0; i < KSZ; i++) {
                    #pragma unroll
                    for (int j = 0; j < KSZ; j++) {
                        const float wv = __ldg(&wc[i * KSZ + j]);
                        const int off = i * HH + j;
                        #pragma unroll
                        for (int k = 0; k < 4; k++)
                            acc[k] = fmaf(__ldg(&imc[base[k] + off]), wv, acc[k]);
                    }
                }
            }

            #pragma unroll
            for (int k = 0; k < 4; k++)
                if (valid[k]) outp[tid + (pass * 4 + k) * 256] = acc[k];
        }
        return;
    }

    // Prologue (independent of xxT): softplus + index math
    __shared__ float sp[KN];
    if (tid < KN) sp[tid] = log1pf(expf(w_sigma[tid]));
    __syncthreads();

    int idx = (blockIdx.x - MU_BLOCKS) * 256 + tid;
    if (idx >= SCALE_TOTAL) return;

    int qv = idx % QV;
    int p  = (idx / QV) % PP;
    int b  = idx / (QV * PP);

    const size_t planeStride = (size_t)PP * PP;
    const float* gsrc = &g_xxT[((size_t)b * PP + p) * PP + qv * 4];
    float* o = sigma + ((size_t)b * KN) * planeStride + (size_t)p * PP + qv * 4;

    // Gate the xxT read on the gram grid's completion (memory-visible).
    asm volatile("griddepcontrol.wait;" ::: "memory");

    const float4 v = __ldcg((const float4*)gsrc);

    #pragma unroll
    for (int kn = 0; kn < KN; kn++) {
        const float s = sp[kn];
        float4 w;
        w.x = v.x * s; w.y = v.y * s; w.z = v.z * s; w.w = v.w * s;
        __stcs((float4*)o, w);
        o += planeStride;
    }
}

extern "C" void kernel_launch(void* const* d_in, const int* in_sizes, int n_in,
                              void* d_out, int out_size)
{
    const float* mu_in   = (const float*)d_in[0];
    const float* w_mu    = (const float*)d_in[1];
    const float* w_sigma = (const float*)d_in[2];

    float* out    = (float*)d_out;
    float* mu_out = out;
    float* sigma  = out + (size_t)BATCH * KN * OH * OH;

    // Primary: gram (plain launch)
    dim3 gridA(NUPPER, 1, BATCH);   // 272 CTAs: one wave at 2/SM
    vdp_gram_kernel<<<gridA, 256>>>(mu_in);

    // Secondary: scale(+mu), launched with programmatic dependency so it can
    // begin occupying SMs as gram drains. xxT readers gate on
    // griddepcontrol.wait; mu blocks overlap gram fully.
    cudaLaunchConfig_t cfg = {};
    cfg.gridDim  = dim3(MU_BLOCKS + SCALE_BLOCKS, 1, 1);
    cfg.blockDim = dim3(256, 1, 1);
    cfg.dynamicSmemBytes = 0;
    cfg.stream = 0;

    cudaLaunchAttribute attrs[1];
    attrs[0].id = cudaLaunchAttributeProgrammaticStreamSerialization;
    attrs[0].val.programmaticStreamSerializationAllowed = 1;
    cfg.attrs = attrs;
    cfg.numAttrs = 1;

    cudaError_t err = cudaLaunchKernelEx(&cfg, vdp_scale_kernel,
                                         w_sigma, mu_in, w_mu, mu_out, sigma);
    if (err != cudaSuccess) {
        // Fallback: plain stream-serialized launch (still correct).
        vdp_scale_kernel<<<MU_BLOCKS + SCALE_BLOCKS, 256>>>(w_sigma, mu_in,
                                                            w_mu, mu_out, sigma);
    }
}